// round 9
// baseline (speedup 1.0000x reference)
#include <cuda_runtime.h>
#include <cuda_bf16.h>
#include <math.h>
#include <cstdint>

#define NB 128
#define NT 128
#define NV 10000
#define NE 256
#define NH 1024
#define ND 128
#define NG 3072   // 3*NH

#define NBLK 128

typedef unsigned long long u64;
typedef __nv_bfloat16 bf16;

// ---------------- scratch ----------------
__device__ float g_table[(size_t)NV * NG];
__device__ float g_hs[(size_t)NB * NT * NH];
__device__ float g_logits[(size_t)NB * NT * NV];
__device__ unsigned g_barcnt;
__device__ bf16 g_hsplit[2][(size_t)NB * 2048];       // [parity][b][hi(1024)|lo(1024)]
// split operands for head GEMMs
__device__ bf16 g_embs[(size_t)NV * (3*NE)];
__device__ bf16 g_gukt[(size_t)NG * (3*NE)];
__device__ bf16 g_hss [(size_t)NB*NT * (3*NH)];
__device__ bf16 g_w1t [(size_t)ND * (3*NH)];
__device__ bf16 g_ds  [(size_t)NB*NT * (3*ND)];
__device__ bf16 g_w2t [(size_t)NV * (3*ND)];

// ================= split/transpose prep (R4 verbatim) =================
__global__ __launch_bounds__(256)
void split_rows(const float* __restrict__ src, int M, int K, bf16* __restrict__ dst)
{
    size_t idx = (size_t)blockIdx.x * 256 + threadIdx.x;
    if (idx >= (size_t)M * K) return;
    int m = (int)(idx / K), k = (int)(idx % K);
    float x = src[idx];
    bf16 h = __float2bfloat16(x);
    bf16 l = __float2bfloat16(x - __bfloat162float(h));
    bf16* d = dst + (size_t)m * 3 * K;
    d[k] = h; d[K + k] = h; d[2*K + k] = l;
}

__global__ __launch_bounds__(256)
void transp_split(const float* __restrict__ src, int K, int N, bf16* __restrict__ dst)
{
    __shared__ float tile[32][33];
    int k0 = blockIdx.y * 32, n0 = blockIdx.x * 32;
    int tx = threadIdx.x & 31, ty = threadIdx.x >> 5;
    for (int i = ty; i < 32; i += 8) {
        int k = k0 + i, n = n0 + tx;
        tile[i][tx] = (k < K && n < N) ? src[(size_t)k * N + n] : 0.0f;
    }
    __syncthreads();
    for (int i = ty; i < 32; i += 8) {
        int n = n0 + i, k = k0 + tx;
        if (n < N && k < K) {
            float x = tile[tx][i];
            bf16 h = __float2bfloat16(x);
            bf16 l = __float2bfloat16(x - __bfloat162float(h));
            bf16* d = dst + (size_t)n * 3 * K;
            d[k] = h; d[K + k] = l; d[2*K + k] = h;
        }
    }
}

// ================= bf16 mma.sync GEMM for head (R4 verbatim) =================
#define GSTR 40

__global__ __launch_bounds__(256)
void gemm_bf16s(const bf16* __restrict__ A, int lda,
                const bf16* __restrict__ Bt, int ldb,
                int M, int N, int K3,
                const float* __restrict__ bias, int relu,
                float* __restrict__ C, int ldc,
                bf16* __restrict__ Cs, int Kout)
{
    __shared__ bf16 As[128 * GSTR];
    __shared__ bf16 Bs[128 * GSTR];

    const int tid  = threadIdx.x;
    const int lane = tid & 31;
    const int warp = tid >> 5;
    const int bm0 = blockIdx.y * 128, bn0 = blockIdx.x * 128;
    const int wm0 = (warp >> 2) * 64, wn0 = (warp & 3) * 32;

    float c[4][4][4];
#pragma unroll
    for (int mi = 0; mi < 4; mi++)
#pragma unroll
        for (int ni = 0; ni < 4; ni++)
#pragma unroll
            for (int q = 0; q < 4; q++) c[mi][ni][q] = 0.0f;

    for (int k0 = 0; k0 < K3; k0 += 32) {
#pragma unroll
        for (int it = 0; it < 2; it++) {
            int idx = tid + 256 * it;
            int r = idx >> 2, seg = (idx & 3) * 8;
            int gm = bm0 + r; if (gm > M-1) gm = M-1;
            uint4 v = *(const uint4*)&A[(size_t)gm * lda + k0 + seg];
            *(uint4*)&As[r * GSTR + seg] = v;
        }
#pragma unroll
        for (int it = 0; it < 2; it++) {
            int idx = tid + 256 * it;
            int r = idx >> 2, seg = (idx & 3) * 8;
            int gn = bn0 + r; if (gn > N-1) gn = N-1;
            uint4 v = *(const uint4*)&Bt[(size_t)gn * ldb + k0 + seg];
            *(uint4*)&Bs[r * GSTR + seg] = v;
        }
        __syncthreads();

#pragma unroll
        for (int ks = 0; ks < 2; ks++) {
            unsigned bfr[4][2];
#pragma unroll
            for (int ni = 0; ni < 4; ni++) {
                const bf16* p = &Bs[(wn0 + ni*8 + (lane >> 2)) * GSTR + ks*16 + (lane & 3)*2];
                bfr[ni][0] = *(const unsigned*)p;
                bfr[ni][1] = *(const unsigned*)(p + 8);
            }
#pragma unroll
            for (int mi = 0; mi < 4; mi++) {
                unsigned a0, a1, a2, a3;
                unsigned saddr = (unsigned)__cvta_generic_to_shared(
                    &As[(wm0 + mi*16 + (lane & 15)) * GSTR + ks*16 + (lane >> 4)*8]);
                asm volatile("ldmatrix.sync.aligned.m8n8.x4.shared.b16 {%0,%1,%2,%3},[%4];"
                             : "=r"(a0), "=r"(a1), "=r"(a2), "=r"(a3) : "r"(saddr));
#pragma unroll
                for (int ni = 0; ni < 4; ni++) {
                    asm volatile(
                        "mma.sync.aligned.m16n8k16.row.col.f32.bf16.bf16.f32 "
                        "{%0,%1,%2,%3},{%4,%5,%6,%7},{%8,%9},{%0,%1,%2,%3};"
                        : "+f"(c[mi][ni][0]), "+f"(c[mi][ni][1]),
                          "+f"(c[mi][ni][2]), "+f"(c[mi][ni][3])
                        : "r"(a0), "r"(a1), "r"(a2), "r"(a3),
                          "r"(bfr[ni][0]), "r"(bfr[ni][1]));
                }
            }
        }
        __syncthreads();
    }

#pragma unroll
    for (int mi = 0; mi < 4; mi++) {
#pragma unroll
        for (int ni = 0; ni < 4; ni++) {
            int r0  = bm0 + wm0 + mi*16 + (lane >> 2);
            int col = bn0 + wn0 + ni*8 + (lane & 3)*2;
#pragma unroll
            for (int q = 0; q < 4; q++) {
                int gm = r0 + (q >> 1) * 8;
                int gn = col + (q & 1);
                if (gm >= M || gn >= N) continue;
                float v = c[mi][ni][q];
                if (bias) v += bias[gn];
                if (relu) v = fmaxf(v, 0.0f);
                if (C) C[(size_t)gm * ldc + gn] = v;
                if (Cs) {
                    bf16 h = __float2bfloat16(v);
                    bf16 l = __float2bfloat16(v - __bfloat162float(h));
                    bf16* d = Cs + (size_t)gm * 3 * Kout;
                    d[gn] = h; d[Kout + gn] = h; d[2*Kout + gn] = l;
                }
            }
        }
    }
}

// ================= persistent GRU (mma.sync, pipelined, 16-warp K-split) ========
__global__ void reset_bar() { g_barcnt = 0u; }

#define GTHREADS 512
#define W_STR 2056                  // bf16 stride of weight rows
#define A_LD  136                   // bf16 stride of staged h rows
#define W_FLOATS_B (24 * W_STR * 2)           // 98688 bytes
#define ABUF_B     (128 * A_LD * 2)           // 34816 bytes per buffer
#define BRS_OFF (W_FLOATS_B + 2 * ABUF_B)
#define TOK_OFF (BRS_OFF + 96)
#define RED_OFF (TOK_OFF + 512)
#define GRU_SMEM_BYTES (RED_OFF + 8 * 32 * 12 * 4)    // + 12288 reduction area

__device__ __forceinline__ void mma16816(float c[4], unsigned a0, unsigned a1,
                                         unsigned a2, unsigned a3,
                                         unsigned b0, unsigned b1) {
    asm volatile(
        "mma.sync.aligned.m16n8k16.row.col.f32.bf16.bf16.f32 "
        "{%0,%1,%2,%3},{%4,%5,%6,%7},{%8,%9},{%0,%1,%2,%3};"
        : "+f"(c[0]), "+f"(c[1]), "+f"(c[2]), "+f"(c[3])
        : "r"(a0), "r"(a1), "r"(a2), "r"(a3), "r"(b0), "r"(b1));
}

__device__ __forceinline__ void gru_gate3(float acc[3][4], const bf16* ab,
                                          const bf16* w_s, int m0, int lane,
                                          int ks2, int woff) {
    unsigned a[2][4];
#pragma unroll
    for (int s = 0; s < 2; s++) {
        unsigned sa = (unsigned)__cvta_generic_to_shared(
            &ab[(m0 + (lane & 15)) * A_LD + ks2*32 + s*16 + (lane >> 4)*8]);
        asm volatile("ldmatrix.sync.aligned.m8n8.x4.shared.b16 {%0,%1,%2,%3},[%4];"
                     : "=r"(a[s][0]), "=r"(a[s][1]), "=r"(a[s][2]), "=r"(a[s][3])
                     : "r"(sa));
    }
#pragma unroll
    for (int g = 0; g < 3; g++) {
        unsigned b4[4];
        unsigned sb = (unsigned)__cvta_generic_to_shared(
            &w_s[(g*8 + (lane & 7)) * W_STR + woff + (lane >> 3)*8]);
        asm volatile("ldmatrix.sync.aligned.m8n8.x4.shared.b16 {%0,%1,%2,%3},[%4];"
                     : "=r"(b4[0]), "=r"(b4[1]), "=r"(b4[2]), "=r"(b4[3])
                     : "r"(sb));
        mma16816(acc[g], a[0][0], a[0][1], a[0][2], a[0][3], b4[0], b4[1]);
        mma16816(acc[g], a[1][0], a[1][1], a[1][2], a[1][3], b4[2], b4[3]);
    }
}

__global__ __launch_bounds__(GTHREADS, 1)
void gru_persist_tc(const int* __restrict__ tokens,
                    const float* __restrict__ gru_rk,
                    const float* __restrict__ br)
{
    extern __shared__ char smc[];
    bf16*  w_s   = (bf16*)smc;                              // [24][W_STR]: [hi|lo]
    bf16*  Asb   = (bf16*)(smc + W_FLOATS_B);               // 2 x [128][A_LD]
    float* br_s  = (float*)(smc + BRS_OFF);
    int*   tok_s = (int*)(smc + TOK_OFF);
    float* red_s = (float*)(smc + RED_OFF);                 // [8*32][12]

    const int tid  = threadIdx.x;
    const int bid  = blockIdx.x;
    const int lane = tid & 31;
    const int warp = tid >> 5;          // 0..15
    const int wlo  = warp & 7;
    const int half = warp >> 3;         // 0: hi-term, 1: lo-term
    const int jb   = bid * 8;
    const int m0   = wlo * 16;

    // resident split weights: w_s[c][k], c = gate*8 + col, k in [hi 1024 | lo 1024]
    for (int idx = tid; idx < 24 * 2048; idx += GTHREADS) {
        int c = idx >> 11, k = idx & 2047;
        float v = gru_rk[(size_t)(k & 1023) * NG + (c >> 3) * NH + jb + (c & 7)];
        bf16 hv = __float2bfloat16(v);
        w_s[c * W_STR + k] = (k < 1024) ? hv : __float2bfloat16(v - __bfloat162float(hv));
    }
    if (tid < 24) br_s[tid] = br[(tid >> 3) * NH + jb + (tid & 7)];
    __syncthreads();

    const int j0 = (lane & 3) * 2;
    const float brz0 = br_s[j0],      brz1 = br_s[j0 + 1];
    const float brr0 = br_s[8 + j0],  brr1 = br_s[8 + j0 + 1];
    const float brh0 = br_s[16 + j0], brh1 = br_s[16 + j0 + 1];

    const int s_seg = (tid & 15) * 8;    // k segment (8 bf16)
    const int s_r0  = tid >> 4;          // row base 0..31, +32 per it

    for (int t = 0; t < NT; t++) {
        float acc[3][4];
#pragma unroll
        for (int g = 0; g < 3; g++)
#pragma unroll
            for (int q = 0; q < 4; q++) acc[g][q] = 0.0f;

        if (tid < 128) tok_s[tid] = tokens[tid * NT + t];

        if (t > 0) {
            const bf16* hsrc = g_hsplit[(t + 1) & 1];
            uint4 pre[4];

            // prologue: stage chunk 0 into buf0
#pragma unroll
            for (int it = 0; it < 4; it++)
                pre[it] = __ldcg((const uint4*)&hsrc[(size_t)(s_r0 + 32*it) * 2048 + s_seg]);
#pragma unroll
            for (int it = 0; it < 4; it++)
                *(uint4*)&Asb[(s_r0 + 32*it) * A_LD + s_seg] = pre[it];
            __syncthreads();

            for (int c = 0; c < 16; c++) {
                // 1) prefetch chunk c+1 into regs
                if (c < 15) {
                    const int cb = (c + 1) * 128;
#pragma unroll
                    for (int it = 0; it < 4; it++)
                        pre[it] = __ldcg((const uint4*)&hsrc[(size_t)(s_r0 + 32*it) * 2048 + cb + s_seg]);
                }
                // 2) mma on chunk c (K-split across warp halves)
                const bf16* ab = Asb + (c & 1) * 128 * A_LD;
                const bool hi = (c < 8);
                const int kg = (hi ? c : c - 8) * 128;
#pragma unroll
                for (int ks2 = 0; ks2 < 4; ks2++) {
                    if (hi) {
                        // half 0: h_hi . w_hi ; half 1: h_hi . w_lo
                        gru_gate3(acc, ab, w_s, m0, lane, ks2,
                                  kg + ks2*32 + half * 1024);
                    } else {
                        // h_lo . w_hi, alternate ks2 between halves
                        if ((ks2 & 1) == half)
                            gru_gate3(acc, ab, w_s, m0, lane, ks2, kg + ks2*32);
                    }
                }
                __syncthreads();
                // 3) store prefetched chunk c+1
                if (c < 15) {
                    bf16* dst = Asb + ((c + 1) & 1) * 128 * A_LD;
#pragma unroll
                    for (int it = 0; it < 4; it++)
                        *(uint4*)&dst[(s_r0 + 32*it) * A_LD + s_seg] = pre[it];
                    __syncthreads();
                }
            }

            // ---- merge half-1 accumulators into half-0
            if (half == 1) {
                float* p = &red_s[(wlo * 32 + lane) * 12];
#pragma unroll
                for (int g = 0; g < 3; g++)
#pragma unroll
                    for (int q = 0; q < 4; q++) p[g*4 + q] = acc[g][q];
            }
            __syncthreads();
            if (half == 0) {
                const float* p = &red_s[(wlo * 32 + lane) * 12];
#pragma unroll
                for (int g = 0; g < 3; g++)
#pragma unroll
                    for (int q = 0; q < 4; q++) acc[g][q] += p[g*4 + q];
            }
        } else {
            __syncthreads();
        }

        // ---- gates: warps 0-7 only; lane owns rows m0+(lane>>2)+{0,8}, cols jb+j0..+1
        if (half == 0) {
            bf16* hout = g_hsplit[t & 1];
#pragma unroll
            for (int rr = 0; rr < 2; rr++) {
                int b = m0 + (lane >> 2) + rr * 8;
                int tok = tok_s[b];
                const float* tab = g_table + (size_t)tok * NG + jb;
                float h2[2];
#pragma unroll
                for (int qq = 0; qq < 2; qq++) {
                    int j = j0 + qq;
                    float rz = acc[0][rr*2 + qq] + (qq ? brz1 : brz0);
                    float rrg= acc[1][rr*2 + qq] + (qq ? brr1 : brr0);
                    float rh = acc[2][rr*2 + qq] + (qq ? brh1 : brh0);
                    float xz = tab[j], xr = tab[NH + j], xh = tab[2*NH + j];
                    float z  = 1.0f / (1.0f + expf(-(xz + rz)));
                    float r  = 1.0f / (1.0f + expf(-(xr + rrg)));
                    float hh = tanhf(xh + r * rh);
                    float hp = (t > 0) ? g_hs[((size_t)b * NT + (t-1)) * NH + jb + j] : 0.0f;
                    h2[qq] = z * hp + (1.0f - z) * hh;
                }
                *(float2*)&g_hs[((size_t)b * NT + t) * NH + jb + j0] = make_float2(h2[0], h2[1]);
                bf16 h0h = __float2bfloat16(h2[0]);
                bf16 h1h = __float2bfloat16(h2[1]);
                bf16 h0l = __float2bfloat16(h2[0] - __bfloat162float(h0h));
                bf16 h1l = __float2bfloat16(h2[1] - __bfloat162float(h1h));
                __nv_bfloat162 ph; ph.x = h0h; ph.y = h1h;
                __nv_bfloat162 pl; pl.x = h0l; pl.y = h1l;
                *(__nv_bfloat162*)&hout[(size_t)b * 2048 + jb + j0]        = ph;
                *(__nv_bfloat162*)&hout[(size_t)b * 2048 + 1024 + jb + j0] = pl;
            }
        }

        // ---- grid barrier
        __syncthreads();
        if (tid == 0) {
            __threadfence();
            atomicAdd(&g_barcnt, 1u);
            const unsigned target = (unsigned)NBLK * (unsigned)(t + 1);
            while (atomicAdd(&g_barcnt, 0u) < target) { }
        }
        __syncthreads();
    }
}

// ================= softmax (R2 verbatim) =================
__global__ __launch_bounds__(256)
void softmax_rows(float* __restrict__ out)
{
    __shared__ float row[NV];
    __shared__ float red[256];
    const int tid = threadIdx.x;
    const size_t r0 = (size_t)blockIdx.x * NV;

    float m = -1e30f;
    for (int v = tid; v < NV; v += 256) {
        float x = g_logits[r0 + v];
        row[v] = x;
        m = fmaxf(m, x);
    }
    red[tid] = m; __syncthreads();
    for (int s = 128; s > 0; s >>= 1) {
        if (tid < s) red[tid] = fmaxf(red[tid], red[tid + s]);
        __syncthreads();
    }
    const float smax = red[0];
    __syncthreads();

    float sum = 0.0f;
    for (int v = tid; v < NV; v += 256) {
        float e = expf((row[v] - smax) * 50.0f);
        row[v] = e;
        sum += e;
    }
    red[tid] = sum; __syncthreads();
    for (int s = 128; s > 0; s >>= 1) {
        if (tid < s) red[tid] += red[tid + s];
        __syncthreads();
    }
    const float inv = 1.0f / red[0];
    for (int v = tid; v < NV; v += 256)
        out[r0 + v] = row[v] * inv;
}

// ================= launch =================
extern "C" void kernel_launch(void* const* d_in, const int* in_sizes, int n_in,
                              void* d_out, int out_size)
{
    const int*   tokens = (const int*)  d_in[0];
    const float* emb    = (const float*)d_in[1];
    const float* gru_k  = (const float*)d_in[2];
    const float* gru_rk = (const float*)d_in[3];
    const float* gru_bi = (const float*)d_in[4];
    const float* gru_br = (const float*)d_in[5];
    const float* w1     = (const float*)d_in[6];
    const float* b1     = (const float*)d_in[7];
    const float* w2     = (const float*)d_in[8];
    const float* b2     = (const float*)d_in[9];
    float* out = (float*)d_out;

    float* tablep = nullptr; cudaGetSymbolAddress((void**)&tablep, g_table);
    float* hsp    = nullptr; cudaGetSymbolAddress((void**)&hsp,    g_hs);
    float* logp   = nullptr; cudaGetSymbolAddress((void**)&logp,   g_logits);
    bf16* embs = nullptr; cudaGetSymbolAddress((void**)&embs, g_embs);
    bf16* gukt = nullptr; cudaGetSymbolAddress((void**)&gukt, g_gukt);
    bf16* hss  = nullptr; cudaGetSymbolAddress((void**)&hss,  g_hss);
    bf16* w1t  = nullptr; cudaGetSymbolAddress((void**)&w1t,  g_w1t);
    bf16* ds   = nullptr; cudaGetSymbolAddress((void**)&ds,   g_ds);
    bf16* w2t  = nullptr; cudaGetSymbolAddress((void**)&w2t,  g_w2t);

    static int smem_set = 0;
    if (!smem_set) {
        cudaFuncSetAttribute(gru_persist_tc, cudaFuncAttributeMaxDynamicSharedMemorySize,
                             GRU_SMEM_BYTES);
        smem_set = 1;
    }

    // 0) split/transpose prep
    split_rows<<<(NV*NE + 255)/256, 256>>>(emb, NV, NE, embs);
    { dim3 g((NG+31)/32, (NE+31)/32);  transp_split<<<g, 256>>>(gru_k, NE, NG, gukt); }
    { dim3 g((ND+31)/32, (NH+31)/32);  transp_split<<<g, 256>>>(w1, NH, ND, w1t); }
    { dim3 g((NV+31)/32, (ND+31)/32);  transp_split<<<g, 256>>>(w2, ND, NV, w2t); }

    // 1) table = emb @ gru_k + gru_bi
    {
        dim3 grid(NG/128, (NV + 127)/128);
        gemm_bf16s<<<grid, 256>>>(embs, 3*NE, gukt, 3*NE, NV, NG, 3*NE,
                                  gru_bi, 0, tablep, NG, nullptr, 0);
    }

    // 2) persistent GRU (mma.sync, 16-warp K-split)
    reset_bar<<<1, 1>>>();
    gru_persist_tc<<<NBLK, GTHREADS, GRU_SMEM_BYTES>>>(tokens, gru_rk, gru_br);

    // 2.5) split hs for head
    split_rows<<<(NB*NT*NH + 255)/256, 256>>>(hsp, NB*NT, NH, hss);

    // 3) d' = split(relu(hs @ w1 + b1))
    {
        dim3 grid(1, (NB*NT)/128);
        gemm_bf16s<<<grid, 256>>>(hss, 3*NH, w1t, 3*NH, NB*NT, ND, 3*NH,
                                  b1, 1, nullptr, 0, ds, ND);
    }

    // 4) logits = d @ w2 + b2
    {
        dim3 grid((NV + 127)/128, (NB*NT)/128);
        gemm_bf16s<<<grid, 256>>>(ds, 3*ND, w2t, 3*ND, NB*NT, NV, 3*ND,
                                  b2, 0, logp, NV, nullptr, 0);
    }

    // 5) softmax
    softmax_rows<<<NB*NT, 256>>>(out);
}